// round 1
// baseline (speedup 1.0000x reference)
#include <cuda_runtime.h>

#define NB 32
#define E  512
#define IND 128
#define OUTD 64
#define NT 3
#define QD 128
#define CD 128   // 2*OUTD

// ---------------- scratch (__device__ globals: no allocs allowed) ----------
__device__ float g_wsrc[NT*NB*IND];
__device__ float g_wdst[NT*NB*IND];
__device__ float g_ssrc[NT*NB*E];
__device__ float g_sdst[NT*NB*E];
__device__ float g_hm[(size_t)NB*E*OUTD];
__device__ float g_rmax[NB*E];
__device__ float g_rinvZ[NB*E];

// ---------------------------------------------------------------------------
// Kernel 1: per (t,n) compute qg = sigmoid(relu(q@W1)@W2), then fold into
//   w_src[i] = sum_o W_type[t,i,o] * qg[o]   * a_type[t,o]
//   w_dst[i] = sum_o W_type[t,i,o] * qg[64+o]* a_type[t,64+o]
// grid = NT*NB blocks, 128 threads
// ---------------------------------------------------------------------------
__global__ void prep_kernel(const float* __restrict__ qv,
                            const float* __restrict__ Wt,
                            const float* __restrict__ at,
                            const float* __restrict__ W1,
                            const float* __restrict__ W2) {
    int t = blockIdx.x / NB, n = blockIdx.x % NB;
    int c = threadIdx.x;                       // 0..127
    __shared__ float sq[QD], sg1[CD], su[CD];

    sq[c] = qv[n*QD + c];
    __syncthreads();

    const float* w1 = W1 + t*QD*CD;
    float acc = 0.f;
    #pragma unroll 8
    for (int q = 0; q < QD; q++) acc += sq[q] * w1[q*CD + c];
    sg1[c] = fmaxf(acc, 0.f);
    __syncthreads();

    const float* w2 = W2 + t*CD*CD;
    acc = 0.f;
    #pragma unroll 8
    for (int q = 0; q < CD; q++) acc += sg1[q] * w2[q*CD + c];
    float qg = 1.f / (1.f + expf(-acc));
    su[c] = qg * at[t*CD + c];                 // a_type (3,128,1)
    __syncthreads();

    const float* W = Wt + (t*IND + c)*OUTD;    // W_type[t, i=c, :]
    float ws = 0.f, wd = 0.f;
    #pragma unroll 8
    for (int o = 0; o < OUTD; o++) {
        float w = W[o];
        ws += w * su[o];
        wd += w * su[OUTD + o];
    }
    g_wsrc[(t*NB + n)*IND + c] = ws;
    g_wdst[(t*NB + n)*IND + c] = wd;
}

// ---------------------------------------------------------------------------
// Kernel 2: s_src[t,n,e] = x[n,e,:] . w_src[t,n,:]  (and dst)
// grid = NB, block = 512 (16 warps); one warp per e, coalesced float4 loads.
// ---------------------------------------------------------------------------
__global__ void ssd_kernel(const float* __restrict__ x) {
    int n = blockIdx.x;
    __shared__ float sw[6][IND];               // 3 src then 3 dst
    int tid = threadIdx.x;
    for (int k = tid; k < 6*IND; k += blockDim.x) {
        int v = k / IND, i = k % IND;
        int t = v % 3;
        sw[v][i] = (v < 3) ? g_wsrc[(t*NB+n)*IND + i] : g_wdst[(t*NB+n)*IND + i];
    }
    __syncthreads();

    int warp = tid >> 5, lane = tid & 31;
    for (int e = warp; e < E; e += 16) {
        const float4 v = ((const float4*)(x + ((size_t)n*E + e)*IND))[lane];
        float acc[6];
        #pragma unroll
        for (int u = 0; u < 6; u++) {
            const float* w = &sw[u][lane*4];
            acc[u] = v.x*w[0] + v.y*w[1] + v.z*w[2] + v.w*w[3];
        }
        #pragma unroll
        for (int off = 16; off > 0; off >>= 1)
            #pragma unroll
            for (int u = 0; u < 6; u++)
                acc[u] += __shfl_xor_sync(0xffffffffu, acc[u], off);
        if (lane == 0) {
            #pragma unroll
            for (int t = 0; t < 3; t++) {
                g_ssrc[(t*NB+n)*E + e] = acc[t];
                g_sdst[(t*NB+n)*E + e] = acc[t+3];
            }
        }
    }
}

// ---------------------------------------------------------------------------
// Kernel 3: h_m[n,e,:] = (x[n,e,:] @ W_type[2]) * mask[n,e]
// grid = (NB, E/64), 256 threads, 4x4 register tile, K=128 fully in smem.
// ---------------------------------------------------------------------------
__global__ void hm_kernel(const float* __restrict__ x,
                          const float* __restrict__ Wt,
                          const float* __restrict__ mask) {
    __shared__ float Ws[IND][OUTD + 4];        // 128 x 68
    __shared__ float Xs[64][IND + 4];          // 64 x 132
    int n = blockIdx.x, e0 = blockIdx.y * 64;
    int tid = threadIdx.x;                     // 256

    const float4* Wg = (const float4*)(Wt + 2*IND*OUTD);
    for (int k = tid; k < IND*OUTD/4; k += 256) {
        float4 v = Wg[k];
        int row = (k*4) / OUTD, col = (k*4) % OUTD;
        *(float4*)&Ws[row][col] = v;
    }
    const float4* Xg = (const float4*)(x + ((size_t)n*E + e0)*IND);
    for (int k = tid; k < 64*IND/4; k += 256) {
        float4 v = Xg[k];
        int row = (k*4) / IND, col = (k*4) % IND;
        *(float4*)&Xs[row][col] = v;
    }
    __syncthreads();

    int dq = tid & 15, eq = tid >> 4;
    int d0 = dq*4, el = eq*4;
    float acc[4][4] = {};
    #pragma unroll 8
    for (int k = 0; k < IND; k++) {
        float4 b = *(const float4*)&Ws[k][d0];
        float a0 = Xs[el+0][k], a1 = Xs[el+1][k], a2 = Xs[el+2][k], a3 = Xs[el+3][k];
        acc[0][0]+=a0*b.x; acc[0][1]+=a0*b.y; acc[0][2]+=a0*b.z; acc[0][3]+=a0*b.w;
        acc[1][0]+=a1*b.x; acc[1][1]+=a1*b.y; acc[1][2]+=a1*b.z; acc[1][3]+=a1*b.w;
        acc[2][0]+=a2*b.x; acc[2][1]+=a2*b.y; acc[2][2]+=a2*b.z; acc[2][3]+=a2*b.w;
        acc[3][0]+=a3*b.x; acc[3][1]+=a3*b.y; acc[3][2]+=a3*b.z; acc[3][3]+=a3*b.w;
    }
    #pragma unroll
    for (int r = 0; r < 4; r++) {
        float mk = mask[n*E + e0 + el + r];
        float4 o = make_float4(acc[r][0]*mk, acc[r][1]*mk, acc[r][2]*mk, acc[r][3]*mk);
        *(float4*)&g_hm[((size_t)n*E + e0 + el + r)*OUTD + d0] = o;
    }
}

// ---------------------------------------------------------------------------
// Kernel 4: per row (n,i): m = max_j score, invZ = 1/sum_j exp(score-m)
// score = adj==0 ? -1e30 : leaky(s_src[t,i]+s_dst[t,j], 0.2),  t = adj-1
// grid = NB*E, block = 512 (one thread per j)
// ---------------------------------------------------------------------------
__global__ void rowstats_kernel(const int* __restrict__ adj) {
    int ni = blockIdx.x;
    int n = ni / E, i = ni % E;
    int j = threadIdx.x;
    __shared__ float ssr[3];
    __shared__ float red[16];
    __shared__ float red2[16];
    if (j < 3) ssr[j] = g_ssrc[(j*NB + n)*E + i];
    __syncthreads();

    int v = adj[(size_t)ni*E + j];
    float score = -1e30f;
    if (v > 0) {
        int t = v - 1;
        float s = ssr[t] + g_sdst[(t*NB + n)*E + j];
        score = (s >= 0.f) ? s : 0.2f*s;
    }
    float m = score;
    #pragma unroll
    for (int off = 16; off > 0; off >>= 1) m = fmaxf(m, __shfl_xor_sync(~0u, m, off));
    if ((j & 31) == 0) red[j >> 5] = m;
    __syncthreads();
    if (j < 32) {
        float t2 = (j < 16) ? red[j] : -1e30f;
        #pragma unroll
        for (int off = 8; off > 0; off >>= 1) t2 = fmaxf(t2, __shfl_xor_sync(~0u, t2, off));
        if (j == 0) red[0] = t2;
    }
    __syncthreads();
    m = red[0];

    float s2 = __expf(score - m);
    #pragma unroll
    for (int off = 16; off > 0; off >>= 1) s2 += __shfl_xor_sync(~0u, s2, off);
    if ((j & 31) == 0) red2[j >> 5] = s2;
    __syncthreads();
    if (j < 32) {
        float t2 = (j < 16) ? red2[j] : 0.f;
        #pragma unroll
        for (int off = 8; off > 0; off >>= 1) t2 += __shfl_xor_sync(~0u, t2, off);
        if (j == 0) { g_rmax[ni] = m; g_rinvZ[ni] = 1.f / t2; }
    }
}

// ---------------------------------------------------------------------------
// Kernel 5: out[n,j,d] = sum_i coef[n,i,j] * h_m[n,i,d], coefs computed
// on the fly from adj + s_src/s_dst + row stats (no 33MB coef tensor).
// grid = (NB, E/64) j-tiles, 256 threads, 4x4 register tile over (j,d).
// ---------------------------------------------------------------------------
__global__ void out_kernel(const int* __restrict__ adj, float* __restrict__ out) {
    int n = blockIdx.x, j0t = blockIdx.y * 64;
    __shared__ float Cs[64][68];               // coef[i_local][j_local]
    __shared__ float Hs[64][68];               // h_m[i_local][d]
    __shared__ float sds[3][64];               // s_dst for this j-tile
    __shared__ float ssr[3][64];               // s_src for this i-chunk
    __shared__ float sm[64], siz[64];
    int tid = threadIdx.x;                     // 256
    int jq = tid & 15, dq = tid >> 4;          // j0 = 4*jq, d0 = 4*dq

    if (tid < 192) {
        int t = tid / 64, j = tid % 64;
        sds[t][j] = g_sdst[(t*NB + n)*E + j0t + j];
    }

    float acc[4][4] = {};
    for (int ic = 0; ic < E; ic += 64) {
        __syncthreads();                       // prev-iter smem reads done
        if (tid < 64) { sm[tid] = g_rmax[n*E + ic + tid]; siz[tid] = g_rinvZ[n*E + ic + tid]; }
        else if (tid < 256) { int t = (tid-64)/64, i = (tid-64)%64;
                              ssr[t][i] = g_ssrc[(t*NB + n)*E + ic + i]; }
        const float4* Hg = (const float4*)(g_hm + ((size_t)n*E + ic)*OUTD);
        for (int k = tid; k < 64*OUTD/4; k += 256) {
            float4 v = Hg[k];
            int row = (k*4) / OUTD, col = (k*4) % OUTD;
            *(float4*)&Hs[row][col] = v;
        }
        __syncthreads();

        // compute coef tile: thread handles 4 i-rows (iq=dq) x 4 j
        #pragma unroll
        for (int r = 0; r < 4; r++) {
            int il = dq*4 + r;
            const int4 a4 = *(const int4*)(adj + ((size_t)n*E + ic + il)*E + j0t + jq*4);
            float m = sm[il], iz = siz[il];
            int vv[4] = {a4.x, a4.y, a4.z, a4.w};
            float c[4];
            #pragma unroll
            for (int q = 0; q < 4; q++) {
                int v = vv[q];
                float score = -1e30f;
                if (v > 0) {
                    int t = v - 1;
                    float s = ssr[t][il] + sds[t][jq*4 + q];
                    score = (s >= 0.f) ? s : 0.2f*s;
                }
                c[q] = __expf(score - m) * iz;
            }
            *(float4*)&Cs[il][jq*4] = make_float4(c[0], c[1], c[2], c[3]);
        }
        __syncthreads();

        #pragma unroll 16
        for (int k = 0; k < 64; k++) {
            float4 a = *(const float4*)&Cs[k][jq*4];
            float4 b = *(const float4*)&Hs[k][dq*4];
            acc[0][0]+=a.x*b.x; acc[0][1]+=a.x*b.y; acc[0][2]+=a.x*b.z; acc[0][3]+=a.x*b.w;
            acc[1][0]+=a.y*b.x; acc[1][1]+=a.y*b.y; acc[1][2]+=a.y*b.z; acc[1][3]+=a.y*b.w;
            acc[2][0]+=a.z*b.x; acc[2][1]+=a.z*b.y; acc[2][2]+=a.z*b.z; acc[2][3]+=a.z*b.w;
            acc[3][0]+=a.w*b.x; acc[3][1]+=a.w*b.y; acc[3][2]+=a.w*b.z; acc[3][3]+=a.w*b.w;
        }
    }

    #pragma unroll
    for (int r = 0; r < 4; r++) {
        *(float4*)&out[((size_t)n*E + j0t + jq*4 + r)*OUTD + dq*4] =
            make_float4(acc[r][0], acc[r][1], acc[r][2], acc[r][3]);
    }
}

// ---------------------------------------------------------------------------
extern "C" void kernel_launch(void* const* d_in, const int* in_sizes, int n_in,
                              void* d_out, int out_size) {
    const float* x    = (const float*)d_in[0];   // input_state (32,512,128)
    const int*   adj  = (const int*)  d_in[1];   // adj (32,512,512)
    const float* qv   = (const float*)d_in[2];   // query_vec (32,128)
    const float* mask = (const float*)d_in[3];   // node_mask (32,512,1)
    const float* Wt   = (const float*)d_in[4];   // W_type (3,128,64)
    const float* at   = (const float*)d_in[5];   // a_type (3,128,1)
    const float* W1   = (const float*)d_in[6];   // qattn_W1 (3,128,128)
    const float* W2   = (const float*)d_in[7];   // qattn_W2 (3,128,128)
    float* out = (float*)d_out;                  // (32,512,64)

    prep_kernel<<<NT*NB, 128>>>(qv, Wt, at, W1, W2);
    ssd_kernel<<<NB, 512>>>(x);
    hm_kernel<<<dim3(NB, E/64), 256>>>(x, Wt, mask);
    rowstats_kernel<<<NB*E, 512>>>(adj);
    out_kernel<<<dim3(NB, E/64), 256>>>(adj, out);
}

// round 2
// speedup vs baseline: 1.4414x; 1.4414x over previous
#include <cuda_runtime.h>

#define NB 32
#define E  512
#define IND 128
#define OUTD 64
#define NT 3
#define QD 128
#define CD 128   // 2*OUTD

// ---------------- scratch (__device__ globals: no allocs allowed) ----------
__device__ float g_wsrc[NT*NB*IND];
__device__ float g_wdst[NT*NB*IND];
__device__ float g_ssrc[NT*NB*E];
__device__ float g_sdst[NT*NB*E];
__device__ float g_hm[(size_t)NB*E*OUTD];
__device__ float g_rmax[NB*E];
__device__ float g_rinvZ[NB*E];

// ---------------------------------------------------------------------------
// Kernel 1: per (t,n) compute qg = sigmoid(relu(q@W1)@W2), then fold into
//   w_src[i] = sum_o W_type[t,i,o] * qg[o]   * a_type[t,o]
//   w_dst[i] = sum_o W_type[t,i,o] * qg[64+o]* a_type[t,64+o]
// ---------------------------------------------------------------------------
__global__ void prep_kernel(const float* __restrict__ qv,
                            const float* __restrict__ Wt,
                            const float* __restrict__ at,
                            const float* __restrict__ W1,
                            const float* __restrict__ W2) {
    int t = blockIdx.x / NB, n = blockIdx.x % NB;
    int c = threadIdx.x;                       // 0..127
    __shared__ float sq[QD], sg1[CD], su[CD];

    sq[c] = qv[n*QD + c];
    __syncthreads();

    const float* w1 = W1 + t*QD*CD;
    float acc = 0.f;
    #pragma unroll 8
    for (int q = 0; q < QD; q++) acc += sq[q] * w1[q*CD + c];
    sg1[c] = fmaxf(acc, 0.f);
    __syncthreads();

    const float* w2 = W2 + t*CD*CD;
    acc = 0.f;
    #pragma unroll 8
    for (int q = 0; q < CD; q++) acc += sg1[q] * w2[q*CD + c];
    float qg = 1.f / (1.f + expf(-acc));
    su[c] = qg * at[t*CD + c];                 // a_type (3,128,1)
    __syncthreads();

    const float* W = Wt + (t*IND + c)*OUTD;    // W_type[t, i=c, :]
    float ws = 0.f, wd = 0.f;
    #pragma unroll 8
    for (int o = 0; o < OUTD; o++) {
        float w = W[o];
        ws += w * su[o];
        wd += w * su[OUTD + o];
    }
    g_wsrc[(t*NB + n)*IND + c] = ws;
    g_wdst[(t*NB + n)*IND + c] = wd;
}

// ---------------------------------------------------------------------------
// Kernel 2 (fused): h_m = (x @ W_type[2]) * mask   AND
//                   s_src/s_dst = x . w_src/w_dst (6 dots per row)
// grid = (NB, E/64), 256 threads. x tile loaded ONCE into smem.
// ---------------------------------------------------------------------------
__global__ void hm_ssd_kernel(const float* __restrict__ x,
                              const float* __restrict__ Wt,
                              const float* __restrict__ mask) {
    __shared__ float Ws[IND][OUTD + 4];        // 128 x 68
    __shared__ float Xs[64][IND + 4];          // 64 x 132
    __shared__ float sw[6][IND];               // folded vectors (3 src, 3 dst)
    int n = blockIdx.x, e0 = blockIdx.y * 64;
    int tid = threadIdx.x;                     // 256

    const float4* Wg = (const float4*)(Wt + 2*IND*OUTD);
    for (int k = tid; k < IND*OUTD/4; k += 256) {
        float4 v = Wg[k];
        int row = (k*4) / OUTD, col = (k*4) % OUTD;
        *(float4*)&Ws[row][col] = v;
    }
    const float4* Xg = (const float4*)(x + ((size_t)n*E + e0)*IND);
    for (int k = tid; k < 64*IND/4; k += 256) {
        float4 v = Xg[k];
        int row = (k*4) / IND, col = (k*4) % IND;
        *(float4*)&Xs[row][col] = v;
    }
    for (int k = tid; k < 6*IND; k += 256) {
        int v = k / IND, i = k % IND;
        int t = v % 3;
        sw[v][i] = (v < 3) ? g_wsrc[(t*NB+n)*IND + i] : g_wdst[(t*NB+n)*IND + i];
    }
    __syncthreads();

    // ---- ssd part: 4 threads per row, k strided by 4 (conflict-free) ----
    {
        int r = tid >> 2, q = tid & 3;         // row 0..63, quarter 0..3
        float a[6] = {0.f,0.f,0.f,0.f,0.f,0.f};
        #pragma unroll 8
        for (int kk = 0; kk < 32; kk++) {
            int k = q + 4*kk;
            float xv = Xs[r][k];
            a[0] += xv * sw[0][k]; a[1] += xv * sw[1][k]; a[2] += xv * sw[2][k];
            a[3] += xv * sw[3][k]; a[4] += xv * sw[4][k]; a[5] += xv * sw[5][k];
        }
        #pragma unroll
        for (int off = 1; off <= 2; off <<= 1)
            #pragma unroll
            for (int u = 0; u < 6; u++)
                a[u] += __shfl_xor_sync(0xffffffffu, a[u], off);
        if (q == 0) {
            int e = e0 + r;
            #pragma unroll
            for (int t = 0; t < 3; t++) {
                g_ssrc[(t*NB+n)*E + e] = a[t];
                g_sdst[(t*NB+n)*E + e] = a[t+3];
            }
        }
    }

    // ---- GEMM part: 4x4 register tile ----
    int dq = tid & 15, eq = tid >> 4;
    int d0 = dq*4, el = eq*4;
    float acc[4][4] = {};
    #pragma unroll 8
    for (int k = 0; k < IND; k++) {
        float4 b = *(const float4*)&Ws[k][d0];
        float a0 = Xs[el+0][k], a1 = Xs[el+1][k], a2 = Xs[el+2][k], a3 = Xs[el+3][k];
        acc[0][0]+=a0*b.x; acc[0][1]+=a0*b.y; acc[0][2]+=a0*b.z; acc[0][3]+=a0*b.w;
        acc[1][0]+=a1*b.x; acc[1][1]+=a1*b.y; acc[1][2]+=a1*b.z; acc[1][3]+=a1*b.w;
        acc[2][0]+=a2*b.x; acc[2][1]+=a2*b.y; acc[2][2]+=a2*b.z; acc[2][3]+=a2*b.w;
        acc[3][0]+=a3*b.x; acc[3][1]+=a3*b.y; acc[3][2]+=a3*b.z; acc[3][3]+=a3*b.w;
    }
    #pragma unroll
    for (int r = 0; r < 4; r++) {
        float mk = mask[n*E + e0 + el + r];
        float4 o = make_float4(acc[r][0]*mk, acc[r][1]*mk, acc[r][2]*mk, acc[r][3]*mk);
        *(float4*)&g_hm[((size_t)n*E + e0 + el + r)*OUTD + d0] = o;
    }
}

// ---------------------------------------------------------------------------
// Kernel 3: row softmax stats. ONE WARP PER ROW, 16 rows/block (same n).
// Coalesced stride-32 adj loads (MLP=16), scores in registers, warp-only
// reductions. s_dst staged in smem (bank = j&31 = lane: conflict-free).
// grid = NB*E/16 = 1024, block = 512
// ---------------------------------------------------------------------------
__global__ void rowstats_kernel(const int* __restrict__ adj) {
    int base = blockIdx.x * 16;                // first flattened row
    int n = base / E;
    __shared__ float sds[3][E];
    int tid = threadIdx.x;
    #pragma unroll
    for (int k = tid; k < 3*E; k += 512)
        sds[k >> 9][k & 511] = g_sdst[((k >> 9)*NB + n)*E + (k & 511)];
    __syncthreads();

    int warp = tid >> 5, lane = tid & 31;
    int row = base + warp;                     // flattened (n,i)
    int i = row & (E-1);
    float sr0 = g_ssrc[(0*NB+n)*E + i];
    float sr1 = g_ssrc[(1*NB+n)*E + i];
    float sr2 = g_ssrc[(2*NB+n)*E + i];
    const int* arow = adj + (size_t)row * E;

    float sc[16];
    #pragma unroll
    for (int k = 0; k < 16; k++) {
        int j = lane + 32*k;
        int v = arow[j];
        float s = -1e30f;
        if (v > 0) {
            float srr = (v == 1) ? sr0 : ((v == 2) ? sr1 : sr2);
            float t2 = srr + sds[v-1][j];
            s = (t2 >= 0.f) ? t2 : 0.2f*t2;
        }
        sc[k] = s;
    }
    float m = sc[0];
    #pragma unroll
    for (int k = 1; k < 16; k++) m = fmaxf(m, sc[k]);
    #pragma unroll
    for (int off = 16; off > 0; off >>= 1) m = fmaxf(m, __shfl_xor_sync(~0u, m, off));
    float sum = 0.f;
    #pragma unroll
    for (int k = 0; k < 16; k++) sum += __expf(sc[k] - m);
    #pragma unroll
    for (int off = 16; off > 0; off >>= 1) sum += __shfl_xor_sync(~0u, sum, off);
    if (lane == 0) { g_rmax[row] = m; g_rinvZ[row] = 1.f / sum; }
}

// ---------------------------------------------------------------------------
// Kernel 4: out[n,j,d] = sum_i coef[n,i,j] * h_m[n,i,d], coefs on the fly.
// grid = (NB, E/64) j-tiles, 256 threads, 4x4 register tile over (j,d).
// ---------------------------------------------------------------------------
__global__ void out_kernel(const int* __restrict__ adj, float* __restrict__ out) {
    int n = blockIdx.x, j0t = blockIdx.y * 64;
    __shared__ float Cs[64][68];               // coef[i_local][j_local]
    __shared__ float Hs[64][68];               // h_m[i_local][d]
    __shared__ float sds[3][64];               // s_dst for this j-tile
    __shared__ float ssr[3][64];               // s_src for this i-chunk
    __shared__ float sm[64], siz[64];
    int tid = threadIdx.x;                     // 256
    int jq = tid & 15, dq = tid >> 4;          // j0 = 4*jq, d0 = 4*dq

    if (tid < 192) {
        int t = tid / 64, j = tid % 64;
        sds[t][j] = g_sdst[(t*NB + n)*E + j0t + j];
    }

    float acc[4][4] = {};
    for (int ic = 0; ic < E; ic += 64) {
        __syncthreads();                       // prev-iter smem reads done
        if (tid < 64) { sm[tid] = g_rmax[n*E + ic + tid]; siz[tid] = g_rinvZ[n*E + ic + tid]; }
        else if (tid < 256) { int t = (tid-64)/64, i = (tid-64)%64;
                              ssr[t][i] = g_ssrc[(t*NB + n)*E + ic + i]; }
        const float4* Hg = (const float4*)(g_hm + ((size_t)n*E + ic)*OUTD);
        for (int k = tid; k < 64*OUTD/4; k += 256) {
            float4 v = Hg[k];
            int row = (k*4) / OUTD, col = (k*4) % OUTD;
            *(float4*)&Hs[row][col] = v;
        }
        __syncthreads();

        // compute coef tile: thread handles 4 i-rows x 4 j
        #pragma unroll
        for (int r = 0; r < 4; r++) {
            int il = dq*4 + r;
            const int4 a4 = *(const int4*)(adj + ((size_t)n*E + ic + il)*E + j0t + jq*4);
            float m = sm[il], iz = siz[il];
            int vv[4] = {a4.x, a4.y, a4.z, a4.w};
            float c[4];
            #pragma unroll
            for (int q = 0; q < 4; q++) {
                int v = vv[q];
                float score = -1e30f;
                if (v > 0) {
                    int t = v - 1;
                    float s = ssr[t][il] + sds[t][jq*4 + q];
                    score = (s >= 0.f) ? s : 0.2f*s;
                }
                c[q] = __expf(score - m) * iz;
            }
            *(float4*)&Cs[il][jq*4] = make_float4(c[0], c[1], c[2], c[3]);
        }
        __syncthreads();

        #pragma unroll 16
        for (int k = 0; k < 64; k++) {
            float4 a = *(const float4*)&Cs[k][jq*4];
            float4 b = *(const float4*)&Hs[k][dq*4];
            acc[0][0]+=a.x*b.x; acc[0][1]+=a.x*b.y; acc[0][2]+=a.x*b.z; acc[0][3]+=a.x*b.w;
            acc[1][0]+=a.y*b.x; acc[1][1]+=a.y*b.y; acc[1][2]+=a.y*b.z; acc[1][3]+=a.y*b.w;
            acc[2][0]+=a.z*b.x; acc[2][1]+=a.z*b.y; acc[2][2]+=a.z*b.z; acc[2][3]+=a.z*b.w;
            acc[3][0]+=a.w*b.x; acc[3][1]+=a.w*b.y; acc[3][2]+=a.w*b.z; acc[3][3]+=a.w*b.w;
        }
    }

    #pragma unroll
    for (int r = 0; r < 4; r++) {
        *(float4*)&out[((size_t)n*E + j0t + jq*4 + r)*OUTD + dq*4] =
            make_float4(acc[r][0], acc[r][1], acc[r][2], acc[r][3]);
    }
}

// ---------------------------------------------------------------------------
extern "C" void kernel_launch(void* const* d_in, const int* in_sizes, int n_in,
                              void* d_out, int out_size) {
    const float* x    = (const float*)d_in[0];   // input_state (32,512,128)
    const int*   adj  = (const int*)  d_in[1];   // adj (32,512,512)
    const float* qv   = (const float*)d_in[2];   // query_vec (32,128)
    const float* mask = (const float*)d_in[3];   // node_mask (32,512,1)
    const float* Wt   = (const float*)d_in[4];   // W_type (3,128,64)
    const float* at   = (const float*)d_in[5];   // a_type (3,128,1)
    const float* W1   = (const float*)d_in[6];   // qattn_W1 (3,128,128)
    const float* W2   = (const float*)d_in[7];   // qattn_W2 (3,128,128)
    float* out = (float*)d_out;                  // (32,512,64)

    prep_kernel<<<NT*NB, 128>>>(qv, Wt, at, W1, W2);
    hm_ssd_kernel<<<dim3(NB, E/64), 256>>>(x, Wt, mask);
    rowstats_kernel<<<NB*E/16, 512>>>(adj);
    out_kernel<<<dim3(NB, E/64), 256>>>(adj, out);
}